// round 2
// baseline (speedup 1.0000x reference)
#include <cuda_runtime.h>
#include <cuda_bf16.h>
#include <cstdint>

// ============================================================================
// QuantizedPatternMatcher — bit-sliced popcount matcher (no tcgen05: the
// harness targets .target sm_103, which rejects all tcgen05/TMEM PTX).
//
//   q(v) = #edges v exceeds, in [0,8) -> 3-bit code
//   matches[m,p] = #d (q_x[m,d] == q_pat[p,d])
// Bit-sliced: 3 bitplanes of 512 bits per row; per u32 word:
//   cnt += popc(~((a0^b0)|(a1^b1)|(a2^b2)))   (4 LOP3 + POPC + IADD)
// Exact integer counts; argmax via packed key (cnt<<10)|(1023-p) reproduces
// first-max (lowest index wins ties) exactly.
// ============================================================================

static constexpr int M_TOTAL = 8192;   // B*S = 4*2048
static constexpr int P_TOTAL = 1024;
static constexpr int D_DIM   = 512;
static constexpr int NW      = 16;     // u32 words per bitplane per row
static constexpr int TILE    = 128;
static constexpr int MT      = M_TOTAL / TILE;  // 64
static constexpr int PT      = P_TOTAL / TILE;  // 8
static constexpr int TILE_U32 = NW * 3 * TILE;  // 6144 u32 = 24 KB per tile

// Scratch (device globals only — no allocation allowed)
__device__ __align__(16) uint32_t g_Acode[MT * TILE_U32];   // 1.5 MB
__device__ __align__(16) uint32_t g_Bcode[PT * TILE_U32];   // 192 KB
__device__ uint32_t g_part[M_TOTAL * PT];                   // per-(m, p-tile) keys

// ------------------------------------------------------------- encoding ----
// One warp per (row, word): lane j quantizes dim 32w+j, 3 ballots build the
// bitplanes. Output layout per tile: [w][plane][row_local] so the match
// kernel's global->smem copy is a straight coalesced uint4 stream.
__global__ void __launch_bounds__(256) encode_kernel(
    const float* __restrict__ src, const float* __restrict__ edges,
    uint32_t* __restrict__ dst, int nrows) {
    int gw   = (blockIdx.x * blockDim.x + threadIdx.x) >> 5;
    int lane = threadIdx.x & 31;
    if (gw >= nrows * NW) return;
    int row = gw >> 4;
    int w   = gw & 15;

    float e0 = __ldg(edges + 0), e1 = __ldg(edges + 1), e2 = __ldg(edges + 2),
          e3 = __ldg(edges + 3), e4 = __ldg(edges + 4), e5 = __ldg(edges + 5),
          e6 = __ldg(edges + 6);
    float v = __ldg(src + (size_t)row * D_DIM + w * 32 + lane);
    int q = (v > e0) + (v > e1) + (v > e2) + (v > e3) + (v > e4) + (v > e5) + (v > e6);

    unsigned b0 = __ballot_sync(0xffffffffu, q & 1);
    unsigned b1 = __ballot_sync(0xffffffffu, q & 2);
    unsigned b2 = __ballot_sync(0xffffffffu, q & 4);
    if (lane == 0) {
        int rt = row >> 7, rl = row & 127;
        uint32_t* base = dst + (size_t)rt * TILE_U32 + (w * 3) * TILE + rl;
        base[0]        = b0;
        base[TILE]     = b1;
        base[2 * TILE] = b2;
    }
}

// --------------------------------------------------------------- matcher ----
// CTA = one 128M x 128P tile. 512 threads; thread (tx, ty) computes 4 M-rows
// (ty*4..+3) x 8 P-cols (two split halves {tx*4..+3} and {64+tx*4..+3} so the
// B vector loads are conflict-free contiguous 16B runs). Fused per-tile argmax
// with shuffle reduce across the 16 tx lanes.
__global__ void __launch_bounds__(512) match_kernel() {
    __shared__ uint32_t sA[TILE_U32];
    __shared__ uint32_t sB[TILE_U32];

    const int tid = threadIdx.x;
    const int pt = blockIdx.x, mt = blockIdx.y;

    const uint4* gA = reinterpret_cast<const uint4*>(g_Acode + (size_t)mt * TILE_U32);
    const uint4* gB = reinterpret_cast<const uint4*>(g_Bcode + (size_t)pt * TILE_U32);
    uint4* s4A = reinterpret_cast<uint4*>(sA);
    uint4* s4B = reinterpret_cast<uint4*>(sB);
#pragma unroll
    for (int i = 0; i < TILE_U32 / 4; i += 512) {
        s4A[i + tid] = gA[i + tid];
        s4B[i + tid] = gB[i + tid];
    }
    __syncthreads();

    const int tx = tid & 15;   // p group
    const int ty = tid >> 4;   // m group (0..31)

    uint32_t acc[4][8];
#pragma unroll
    for (int mi = 0; mi < 4; mi++)
#pragma unroll
        for (int pi = 0; pi < 8; pi++) acc[mi][pi] = 0;

#pragma unroll 1
    for (int w = 0; w < NW; w++) {
        uint32_t a[3][4], b[3][8];
#pragma unroll
        for (int pl = 0; pl < 3; pl++) {
            const int rowbase = (w * 3 + pl) * TILE;
            uint4 av = *reinterpret_cast<const uint4*>(&sA[rowbase + ty * 4]);
            a[pl][0] = av.x; a[pl][1] = av.y; a[pl][2] = av.z; a[pl][3] = av.w;
            uint4 b0 = *reinterpret_cast<const uint4*>(&sB[rowbase + tx * 4]);
            uint4 b1 = *reinterpret_cast<const uint4*>(&sB[rowbase + 64 + tx * 4]);
            b[pl][0] = b0.x; b[pl][1] = b0.y; b[pl][2] = b0.z; b[pl][3] = b0.w;
            b[pl][4] = b1.x; b[pl][5] = b1.y; b[pl][6] = b1.z; b[pl][7] = b1.w;
        }
#pragma unroll
        for (int mi = 0; mi < 4; mi++)
#pragma unroll
            for (int pi = 0; pi < 8; pi++) {
                uint32_t t0 = a[0][mi] ^ b[0][pi];
                uint32_t t1 = a[1][mi] ^ b[1][pi];
                uint32_t t2 = a[2][mi] ^ b[2][pi];
                acc[mi][pi] += (uint32_t)__popc(~(t0 | t1 | t2));
            }
    }

    // Fused argmax: key = (cnt << 10) | (1023 - p_global). max(key) == first-max.
#pragma unroll
    for (int mi = 0; mi < 4; mi++) {
        uint32_t key = 0;
#pragma unroll
        for (int pi = 0; pi < 8; pi++) {
            int p = pt * TILE + (pi >> 2) * 64 + tx * 4 + (pi & 3);
            uint32_t k = (acc[mi][pi] << 10) | (uint32_t)(1023 - p);
            key = key > k ? key : k;
        }
#pragma unroll
        for (int off = 8; off >= 1; off >>= 1) {
            uint32_t o = __shfl_xor_sync(0xffffffffu, key, off);
            key = key > o ? key : o;
        }
        if (tx == 0) {
            int m = mt * TILE + ty * 4 + mi;
            g_part[m * PT + pt] = key;
        }
    }
}

// -------------------------------------------------------------- finalize ----
__global__ void __launch_bounds__(256) finalize_kernel(float* __restrict__ out) {
    int m = blockIdx.x * 256 + threadIdx.x;
    if (m >= M_TOTAL) return;
    uint32_t best = 0;
#pragma unroll
    for (int t = 0; t < PT; t++) {
        uint32_t k = g_part[m * PT + t];
        best = best > k ? best : k;
    }
    out[m]           = (float)(1023u - (best & 1023u));            // best_patterns
    out[M_TOTAL + m] = (float)(best >> 10) * (1.0f / 512.0f);      // match_scores
}

// ---------------------------------------------------------------- launch ----
extern "C" void kernel_launch(void* const* d_in, const int* in_sizes, int n_in,
                              void* d_out, int out_size) {
    const float* x     = (const float*)d_in[0];
    const float* pat   = (const float*)d_in[1];
    const float* edges = (const float*)d_in[2];

    uint32_t* gA;
    uint32_t* gB;
    cudaGetSymbolAddress((void**)&gA, g_Acode);
    cudaGetSymbolAddress((void**)&gB, g_Bcode);

    // encode A: 8192 rows * 16 words = 131072 warps -> 16384 blocks of 256
    encode_kernel<<<(M_TOTAL * NW) / 8, 256>>>(x, edges, gA, M_TOTAL);
    // encode B: 1024 rows * 16 words = 16384 warps -> 2048 blocks
    encode_kernel<<<(P_TOTAL * NW) / 8, 256>>>(pat, edges, gB, P_TOTAL);
    // match: 8 p-tiles x 64 m-tiles
    match_kernel<<<dim3(PT, MT), 512>>>();
    finalize_kernel<<<M_TOTAL / 256, 256>>>((float*)d_out);
}

// round 3
// speedup vs baseline: 1.0485x; 1.0485x over previous
#include <cuda_runtime.h>
#include <cuda_bf16.h>
#include <cstdint>

// ============================================================================
// QuantizedPatternMatcher — bit-sliced popcount matcher, 2-kernel fused form.
//   q(v) = #edges v exceeds (3-bit code); matches[m,p] = #d q_x==q_pat
// Per u32 word (32 dims): eq = LOP3-chain(a0^b0, a1^b1, a2^b2) -> popc -> add.
// Argmax fused: key = (cnt<<10)|(1023-p); atomicMax per m; last CTA converts.
// ============================================================================

static constexpr int M_TOTAL = 8192;
static constexpr int P_TOTAL = 1024;
static constexpr int D_DIM   = 512;
static constexpr int NW      = 16;              // u32 words per plane per row
static constexpr int TR      = 64;              // tile rows (both M and P)
static constexpr int MT      = M_TOTAL / TR;    // 128
static constexpr int PT      = P_TOTAL / TR;    // 16
static constexpr int TILE_U32 = NW * 3 * TR;    // 3072 u32 = 12 KB per tile
static constexpr int NCTAS   = MT * PT;         // 2048

__device__ __align__(16) uint32_t g_Acode[MT * TILE_U32];   // 1.5 MB
__device__ __align__(16) uint32_t g_Bcode[PT * TILE_U32];   // 192 KB
__device__ uint32_t g_key[M_TOTAL];
__device__ unsigned int g_ctr;

// NOR-of-xors via guaranteed 3-LOP3 chain.
__device__ __forceinline__ uint32_t eq3(uint32_t a0, uint32_t b0,
                                        uint32_t a1, uint32_t b1,
                                        uint32_t a2, uint32_t b2) {
    uint32_t x, y, z;
    asm("lop3.b32 %0, %1, %2, %3, 0x3C;" : "=r"(x) : "r"(a0), "r"(b0), "r"(0u)); // a^b
    asm("lop3.b32 %0, %1, %2, %3, 0xBE;" : "=r"(y) : "r"(a1), "r"(b1), "r"(x));  // (a^b)|c
    asm("lop3.b32 %0, %1, %2, %3, 0x41;" : "=r"(z) : "r"(a2), "r"(b2), "r"(y));  // ~((a^b)|c)
    return z;
}

// ------------------------------------------------------------- encoding ----
// One warp per (row, word). Ballots build 3 bitplanes. Tile layout
// [tile][w][plane][row_local(64)] -> match kernel copies are pure uint4 streams.
// Block 0 additionally zeroes g_key / g_ctr for this replay.
__global__ void __launch_bounds__(256) encode_kernel(
    const float* __restrict__ x, const float* __restrict__ pat,
    const float* __restrict__ edges) {
    if (blockIdx.x == 0) {
        for (int i = threadIdx.x; i < M_TOTAL; i += 256) g_key[i] = 0u;
        if (threadIdx.x == 0) g_ctr = 0u;
    }
    int gw   = blockIdx.x * 8 + (threadIdx.x >> 5);
    int lane = threadIdx.x & 31;

    const float* src;
    uint32_t* dst;
    int row, w;
    if (gw < M_TOTAL * NW) {
        src = x;   dst = g_Acode; row = gw >> 4; w = gw & 15;
    } else {
        gw -= M_TOTAL * NW;
        src = pat; dst = g_Bcode; row = gw >> 4; w = gw & 15;
    }

    float e0 = __ldg(edges + 0), e1 = __ldg(edges + 1), e2 = __ldg(edges + 2),
          e3 = __ldg(edges + 3), e4 = __ldg(edges + 4), e5 = __ldg(edges + 5),
          e6 = __ldg(edges + 6);
    float v = __ldg(src + (size_t)row * D_DIM + w * 32 + lane);
    int q = (v > e0) + (v > e1) + (v > e2) + (v > e3) + (v > e4) + (v > e5) + (v > e6);

    unsigned b0 = __ballot_sync(0xffffffffu, q & 1);
    unsigned b1 = __ballot_sync(0xffffffffu, q & 2);
    unsigned b2 = __ballot_sync(0xffffffffu, q & 4);
    if (lane == 0) {
        int rt = row >> 6, rl = row & 63;
        uint32_t* base = dst + (size_t)rt * TILE_U32 + (w * 3) * TR + rl;
        base[0]      = b0;
        base[TR]     = b1;
        base[2 * TR] = b2;
    }
}

// --------------------------------------------------------------- matcher ----
// CTA = 64M x 64P tile, 256 threads (tx 0..15 = p-group, ty 0..15 = m-group),
// each thread 4M x 4P. Fused argmax -> atomicMax(g_key[m]); last CTA emits out.
__global__ void __launch_bounds__(256) match_kernel(float* __restrict__ out) {
    __shared__ uint32_t sA[TILE_U32];
    __shared__ uint32_t sB[TILE_U32];
    __shared__ bool s_last;

    const int tid = threadIdx.x;
    const int pt = blockIdx.x, mt = blockIdx.y;

    const uint4* gA = reinterpret_cast<const uint4*>(g_Acode + (size_t)mt * TILE_U32);
    const uint4* gB = reinterpret_cast<const uint4*>(g_Bcode + (size_t)pt * TILE_U32);
    uint4* s4A = reinterpret_cast<uint4*>(sA);
    uint4* s4B = reinterpret_cast<uint4*>(sB);
#pragma unroll
    for (int i = 0; i < TILE_U32 / 4; i += 256) {
        s4A[i + tid] = gA[i + tid];
        s4B[i + tid] = gB[i + tid];
    }
    __syncthreads();

    const int tx = tid & 15;
    const int ty = tid >> 4;

    uint32_t acc[4][4];
#pragma unroll
    for (int mi = 0; mi < 4; mi++)
#pragma unroll
        for (int pi = 0; pi < 4; pi++) acc[mi][pi] = 0;

#pragma unroll 2
    for (int w = 0; w < NW; w++) {
        uint32_t a[3][4], b[3][4];
#pragma unroll
        for (int pl = 0; pl < 3; pl++) {
            const int rowbase = (w * 3 + pl) * TR;
            uint4 av = *reinterpret_cast<const uint4*>(&sA[rowbase + ty * 4]);
            a[pl][0] = av.x; a[pl][1] = av.y; a[pl][2] = av.z; a[pl][3] = av.w;
            uint4 bv = *reinterpret_cast<const uint4*>(&sB[rowbase + tx * 4]);
            b[pl][0] = bv.x; b[pl][1] = bv.y; b[pl][2] = bv.z; b[pl][3] = bv.w;
        }
#pragma unroll
        for (int mi = 0; mi < 4; mi++)
#pragma unroll
            for (int pi = 0; pi < 4; pi++)
                acc[mi][pi] += (uint32_t)__popc(
                    eq3(a[0][mi], b[0][pi], a[1][mi], b[1][pi], a[2][mi], b[2][pi]));
    }

    // key = (cnt<<10)|(1023-p): max == first-max (lowest index wins ties).
#pragma unroll
    for (int mi = 0; mi < 4; mi++) {
        uint32_t key = 0;
#pragma unroll
        for (int pi = 0; pi < 4; pi++) {
            int p = pt * TR + tx * 4 + pi;
            uint32_t k = (acc[mi][pi] << 10) | (uint32_t)(1023 - p);
            key = key > k ? key : k;
        }
#pragma unroll
        for (int off = 8; off >= 1; off >>= 1) {   // reduce over the 16 tx lanes
            uint32_t o = __shfl_xor_sync(0xffffffffu, key, off);
            key = key > o ? key : o;
        }
        if (tx == 0) {
            int m = mt * TR + ty * 4 + mi;
            atomicMax(&g_key[m], key);
        }
    }

    // Last CTA converts keys -> (best_patterns, match_scores).
    __threadfence();
    if (tid == 0)
        s_last = (atomicAdd(&g_ctr, 1u) == (unsigned)(NCTAS - 1));
    __syncthreads();
    if (s_last) {
        __threadfence();   // acquire all g_key updates
        for (int m = tid; m < M_TOTAL; m += 256) {
            uint32_t best = g_key[m];
            out[m]           = (float)(1023u - (best & 1023u));
            out[M_TOTAL + m] = (float)(best >> 10) * (1.0f / 512.0f);
        }
    }
}

// ---------------------------------------------------------------- launch ----
extern "C" void kernel_launch(void* const* d_in, const int* in_sizes, int n_in,
                              void* d_out, int out_size) {
    const float* x     = (const float*)d_in[0];
    const float* pat   = (const float*)d_in[1];
    const float* edges = (const float*)d_in[2];

    // (8192 + 1024) rows * 16 words = 147456 warps -> 18432 blocks of 8 warps
    encode_kernel<<<(M_TOTAL + P_TOTAL) * NW / 8, 256>>>(x, pat, edges);
    match_kernel<<<dim3(PT, MT), 256>>>((float*)d_out);
}